// round 17
// baseline (speedup 1.0000x reference)
#include <cuda_runtime.h>
#include <cstdint>

// NCC loss, sliding-window, 4 px/thread, packed-pair h-sums + bf16 ring.
//
// Block: 128 threads = 4 independent warps; warp owns a 128-px-wide, HS=32-row
// strip (40 row pushes); thread owns 4 adjacent x outputs. Per input row:
//   - row segments (136 floats of I and J incl. x-halo) land in a warp-private
//     4-deep smem staging ring via cp.async.cg 16B (zero-fill OOB chunks);
//     distance-3 prefetch, wait_group 3, __syncwarp only.
//   - windows arrive as natural f32x2 register pairs (T_k); product channels
//     use 6 FMUL2 pair-products (not 12 FMUL); all channels use an A-scheme
//     9-tap sum (A = t2..t9 via 3 FADD2 + 1 lane add, then 8 corrections).
//   - vertical 9-row sliding sums, 9-deep ring, hybrid storage:
//       channels I, J      -> registers (9 x 2 u32 bf16x2, static indices)
//       channels I2,J2,IJ  -> smem (8B = 2 x bf16x2, LDS.64/STS.64)
//     Ring values are bf16x2: pack = 1 cvt.rn.bf16x2.f32 per pair; unpack =
//     SHL/AND (lat-4 ALU) instead of F2F (lat ~20). run (packed f32x2 per
//     pixel-pair) adds fp32 h and subtracts the bf16-rounded value 9 rows
//     later (RN noise, cancels in the global mean).
//   - emit: packed-f32x2 cc per pixel-pair; fractions grouped over 4 rows
//     -> one rcp.approx per 8 px.
// 512 blocks x 45.1 KB smem, regs<=128 -> grid-limited ~3.5 blocks/SM.
// Finalize fused via double atomicAdd + arrival counter. ONE launch.

#define IMG   1024
#define NB    8
#define HS    32
#define TPB   128
#define NWB   4
#define NPUSH (HS + 8)        // 40 = 4 + 4*9
#define SEGF  136             // floats staged per warp-row per array
#define NBUF  4               // staging ring depth (distance-3 prefetch)
#define RSLOT 9
#define NSC   3               // smem ring channels (I2, J2, IJ)
#define GX    2               // 2 x (4 warps x 128 px) = 1024
#define GY    (IMG / HS)      // 32
#define NBLK  (GX * GY * NB)  // 512

#define STG_FLOATS (NBUF * NWB * 2 * SEGF)                 // 4352
#define RING_U64   (RSLOT * NSC * TPB)                     // 3456
#define SMEM_BYTES ((STG_FLOATS + 2 * RING_U64 + 4) * 4)   // 45072 B

typedef unsigned long long ull;

__device__ double       g_accum;
__device__ unsigned int g_cnt;

__device__ __forceinline__ ull pk2(float lo, float hi) {
    ull o;
    asm("mov.b64 %0, {%1, %2};" : "=l"(o)
        : "r"(__float_as_uint(lo)), "r"(__float_as_uint(hi)));
    return o;
}
__device__ __forceinline__ float2 upk2(ull v) {
    unsigned a, b;
    asm("mov.b64 {%0, %1}, %2;" : "=r"(a), "=r"(b) : "l"(v));
    return make_float2(__uint_as_float(a), __uint_as_float(b));
}
#define FADD2(o,a,b)   asm("add.rn.f32x2 %0,%1,%2;"    : "=l"(o) : "l"(a), "l"(b))
#define FMUL2(o,a,b)   asm("mul.rn.f32x2 %0,%1,%2;"    : "=l"(o) : "l"(a), "l"(b))
#define FFMA2(o,a,b,c) asm("fma.rn.f32x2 %0,%1,%2,%3;" : "=l"(o) : "l"(a), "l"(b), "l"(c))

// bf16x2 pack/unpack: pack = 1 cvt; unpack = pure ALU bit ops (bf16 is the
// top 16 bits of f32, so lo = v<<16, hi = v & 0xFFFF0000).
__device__ __forceinline__ uint32_t pkbf(float lo, float hi) {
    uint32_t r;
    asm("cvt.rn.bf16x2.f32 %0, %1, %2;" : "=r"(r) : "f"(hi), "f"(lo));
    return r;
}
__device__ __forceinline__ float bflo(uint32_t v) {
    return __uint_as_float(v << 16);
}
__device__ __forceinline__ float bfhi(uint32_t v) {
    return __uint_as_float(v & 0xFFFF0000u);
}

__device__ __forceinline__ void cp16(uint32_t dst, const float* src, uint32_t sz) {
    asm volatile("cp.async.cg.shared.global [%0], [%1], 16, %2;"
                 :: "r"(dst), "l"(src), "r"(sz));
}
#define CP_COMMIT() asm volatile("cp.async.commit_group;" ::: "memory")
#define CP_WAIT3()  asm volatile("cp.async.wait_group 3;" ::: "memory")

__global__ __launch_bounds__(TPB, 4) void ncc_main_kernel(
    const float* __restrict__ I, const float* __restrict__ J,
    float* __restrict__ out)
{
    extern __shared__ __align__(16) float dyn[];
    float* warpsum = dyn + STG_FLOATS + 2 * RING_U64;

    const int tid  = threadIdx.x;
    const int lane = tid & 31;
    const int w    = tid >> 5;
    const int W0   = blockIdx.x * 512 + w * 128;
    const int Y0   = blockIdx.y * HS;
    const size_t imgoff = (size_t)blockIdx.z * IMG * IMG;

    uint32_t smem_u32;
    asm("{ .reg .u64 t; cvta.to.shared.u64 t, %1; cvt.u32.u64 %0, t; }"
        : "=r"(smem_u32) : "l"(dyn));

    // ---- cp.async chunk assignment: 34 float4 chunks per array per warp-row
    const int  cA   = lane;            // I chunks 0..31
    const int  gxA  = W0 - 4 + 4 * cA;
    const bool vAok = (gxA >= 0) && (gxA <= IMG - 4);
    const float* pbaseA = I + imgoff + (vAok ? gxA : 0);
    const uint32_t dstA0 = smem_u32 + ((w * 2 + 0) * SEGF + 4 * cA) * 4;

    const bool bIsI = lane < 2;        // chunks 32,33 are I; then J 0..29
    const int  cB   = bIsI ? (32 + lane) : (lane - 2);
    const int  gxB  = W0 - 4 + 4 * cB;
    const bool vBok = (gxB >= 0) && (gxB <= IMG - 4);
    const float* pbaseB = (bIsI ? I : J) + imgoff + (vBok ? gxB : 0);
    const uint32_t dstB0 = smem_u32 + ((w * 2 + (bIsI ? 0 : 1)) * SEGF + 4 * cB) * 4;

    const bool hasC = lane < 4;        // J chunks 30..33
    const int  cC   = 30 + lane;
    const int  gxC  = W0 - 4 + 4 * cC;
    const bool vCok = (gxC >= 0) && (gxC <= IMG - 4);
    const float* pbaseC = J + imgoff + (vCok ? gxC : 0);
    const uint32_t dstC0 = smem_u32 + ((w * 2 + 1) * SEGF + 4 * cC) * 4;

    const uint32_t BUFSTRIDE = NWB * 2 * SEGF * 4;   // 4352 bytes

    // ---- smem ring base (channels 2..4), 8B entry = 4 px as 2 x bf16x2
    ull* ringT = (ull*)(dyn + STG_FLOATS) + tid;
#pragma unroll
    for (int s = 0; s < RSLOT; s++)
#pragma unroll
        for (int c = 0; c < NSC; c++)
            ringT[(s * NSC + c) * TPB] = 0ull;

    // ---- register ring (channels 0,1 = I, J): static indices, bf16x2 packs
    uint32_t rgl[2][RSLOT], rgh[2][RSLOT];
#pragma unroll
    for (int s = 0; s < RSLOT; s++) {
        rgl[0][s] = 0u; rgh[0][s] = 0u;
        rgl[1][s] = 0u; rgh[1][s] = 0u;
    }

    // ---- constants / state
    const ull NEG1   = pk2(-1.0f, -1.0f);
    const ull MINV81 = pk2(-1.0f / 81.0f, -1.0f / 81.0f);
    const ull EPS2   = pk2(1e-5f, 1e-5f);
    ull run[5][2];
#pragma unroll
    for (int c = 0; c < 5; c++) { run[c][0] = 0ull; run[c][1] = 0ull; }

    float acc = 0.f;
    float gn[2] = {0.f, 0.f}, gd[2] = {1.f, 1.f};

    // ---- stage: push rr -> input row Y0-4+rr (clamped addr, zero-fill OOB)
    auto stage = [&](int rr) {
        const int yin  = Y0 - 4 + rr;
        const bool yok = (unsigned)yin < (unsigned)IMG;
        const int  yc  = min(max(yin, 0), IMG - 1);
        const uint32_t off  = (uint32_t)yc << 10;
        const uint32_t boff = (uint32_t)(rr & (NBUF - 1)) * BUFSTRIDE;
        cp16(dstA0 + boff, pbaseA + off, (yok && vAok) ? 16u : 0u);
        cp16(dstB0 + boff, pbaseB + off, (yok && vBok) ? 16u : 0u);
        if (hasC)
            cp16(dstC0 + boff, pbaseC + off, (yok && vCok) ? 16u : 0u);
        CP_COMMIT();
    };

    // ---- A-scheme 9-tap sums over 6 f32x2 pairs P[0..5] (taps t0..t11):
    //   A = t2+..+t9 (pairs P1..P4); h0..h3 by short corrections.
    auto hsum = [&](const ull* P, float* h) {
        ull S;
        FADD2(S, P[1], P[2]);
        FADD2(S, S, P[3]);
        FADD2(S, S, P[4]);
        float2 s  = upk2(S);
        float  A  = s.x + s.y;              // t2..t9
        float2 p0 = upk2(P[0]);             // t0, t1
        float2 p1 = upk2(P[1]);             // t2, t3
        float2 p4 = upk2(P[4]);             // t8, t9
        float2 p5 = upk2(P[5]);             // t10, t11
        h[0] = (p0.x + p0.y) + (A - p4.y);  // t0..t8
        h[1] = p0.y + A;                    // t1..t9
        h[2] = A + p5.x;                    // t2..t10
        h[3] = (A - p1.x) + (p5.x + p5.y);  // t3..t11
    };

    // ---- per-push body; slot is a compile-time constant at every call site
    auto body = [&](int r, int slot, bool emitOK) {
        if (r + 3 < NPUSH) stage(r + 3);
        else               CP_COMMIT();
        CP_WAIT3();
        __syncwarp();

        // 12-float windows (4 px) from 3 LDS.128 per array
        const int buf = r & (NBUF - 1);
        const float4* fI4 = (const float4*)(dyn + (buf * NWB + w) * 2 * SEGF);
        const float4* fJ4 = fI4 + SEGF / 4;
        float4 ia = fI4[lane], ib = fI4[lane + 1], ic = fI4[lane + 2];
        float4 ja = fJ4[lane], jb = fJ4[lane + 1], jc = fJ4[lane + 2];

        // natural f32x2 pairs
        ull TI[6] = { pk2(ia.x, ia.y), pk2(ia.z, ia.w), pk2(ib.x, ib.y),
                      pk2(ib.z, ib.w), pk2(ic.x, ic.y), pk2(ic.z, ic.w) };
        ull TJ[6] = { pk2(ja.x, ja.y), pk2(ja.z, ja.w), pk2(jb.x, jb.y),
                      pk2(jb.z, jb.w), pk2(jc.x, jc.y), pk2(jc.z, jc.w) };

        // pair-products for the squared channels: 6 FMUL2 each
        ull QII[6], QJJ[6], QIJ[6];
#pragma unroll
        for (int k = 0; k < 6; k++) {
            FMUL2(QII[k], TI[k], TI[k]);
            FMUL2(QJJ[k], TJ[k], TJ[k]);
            FMUL2(QIJ[k], TI[k], TJ[k]);
        }

        float h[5][4];
        hsum(TI,  h[0]);
        hsum(TJ,  h[1]);
        hsum(QII, h[2]);
        hsum(QJJ, h[3]);
        hsum(QIJ, h[4]);

        // run update shared by both ring kinds (old = bf16x2 packs)
        auto upd = [&](int c, uint32_t olo, uint32_t ohi) {
            ull od0 = pk2(bflo(olo), bfhi(olo));
            ull od1 = pk2(bflo(ohi), bfhi(ohi));
            ull h01 = pk2(h[c][0], h[c][1]);
            ull h23 = pk2(h[c][2], h[c][3]);
            FADD2(run[c][0], run[c][0], h01);
            FFMA2(run[c][0], od0, NEG1, run[c][0]);
            FADD2(run[c][1], run[c][1], h23);
            FFMA2(run[c][1], od1, NEG1, run[c][1]);
        };

        // channels 0,1: register ring (slot literal -> regs)
#pragma unroll
        for (int c = 0; c < 2; c++) {
            uint32_t olo = rgl[c][slot], ohi = rgh[c][slot];
            rgl[c][slot] = pkbf(h[c][0], h[c][1]);
            rgh[c][slot] = pkbf(h[c][2], h[c][3]);
            upd(c, olo, ohi);
        }
        // channels 2..4: smem ring
#pragma unroll
        for (int c = 2; c < 5; c++) {
            ull* rp  = ringT + (slot * NSC + (c - 2)) * TPB;
            ull  old = *rp;                               // LDS.64
            uint32_t nlo = pkbf(h[c][0], h[c][1]);
            uint32_t nhi = pkbf(h[c][2], h[c][3]);
            ull nw;
            asm("mov.b64 %0, {%1, %2};" : "=l"(nw) : "r"(nlo), "r"(nhi));
            *rp = nw;                                     // STS.64
            uint32_t olo, ohi;
            asm("mov.b64 {%0, %1}, %2;" : "=r"(olo), "=r"(ohi) : "l"(old));
            upd(c, olo, ohi);
        }

        // emit output row oy = Y0 + (r - 8)
        if (emitOK) {
            const int cnt = (r - 8) & 3;
#pragma unroll
            for (int p = 0; p < 2; p++) {
                ull t, u, cross2, iv2, jv2, n2, d2;
                FMUL2(t, run[0][p], MINV81);              // -si/81
                FFMA2(cross2, t, run[1][p], run[4][p]);   // SIJ - si*sj/81
                FFMA2(iv2,    t, run[0][p], run[2][p]);   // SI2 - si^2/81
                FMUL2(u, run[1][p], MINV81);              // -sj/81
                FFMA2(jv2,    u, run[1][p], run[3][p]);   // SJ2 - sj^2/81
                FMUL2(n2, cross2, cross2);
                FFMA2(d2, iv2, jv2, EPS2);
                float2 n = upk2(n2), d = upk2(d2);
                float rowN = fmaf(n.x, d.y, n.y * d.x);
                float rowD = d.x * d.y;
                if (cnt == 0) { gn[p] = rowN; gd[p] = rowD; }
                else { gn[p] = fmaf(gn[p], rowD, rowN * gd[p]); gd[p] *= rowD; }
                if (cnt == 3) {
                    float rc;
                    asm("rcp.approx.f32 %0, %1;" : "=f"(rc) : "f"(gd[p]));
                    acc = fmaf(gn[p], rc, acc);
                }
            }
        }
    };

    // ---- prologue: fill pipeline 3 deep, peel pushes 0..3 (slots 0..3)
    stage(0); stage(1); stage(2);
    body(0, 0, false);
    body(1, 1, false);
    body(2, 2, false);
    body(3, 3, false);

    // ---- main: 4 x unroll-9; slot = (4+s) % 9 compile-time
#pragma unroll 1
    for (int m = 0; m < 4; m++) {
#pragma unroll
        for (int s = 0; s < 9; s++) {
            const int r = 4 + 9 * m + s;
            const bool emitOK = (s >= 4) ? true : (m > 0);
            body(r, (4 + s) % 9, emitOK);
        }
    }

    // ---- block reduction + fused finalize
#pragma unroll
    for (int off = 16; off > 0; off >>= 1)
        acc += __shfl_down_sync(0xFFFFFFFFu, acc, off);
    if (lane == 0) warpsum[w] = acc;
    __syncthreads();
    if (tid == 0) {
        float v = warpsum[0] + warpsum[1] + warpsum[2] + warpsum[3];
        atomicAdd(&g_accum, (double)v);
        __threadfence();
        unsigned prev = atomicAdd(&g_cnt, 1u);
        if (prev == NBLK - 1) {               // last block finalizes + resets
            double tot = atomicAdd(&g_accum, 0.0);
            out[0] = (float)(tot / (double)((size_t)NB * IMG * IMG));
            g_accum = 0.0;
            g_cnt   = 0u;
        }
    }
}

extern "C" void kernel_launch(void* const* d_in, const int* in_sizes, int n_in,
                              void* d_out, int out_size) {
    const float* I = (const float*)d_in[0];
    const float* J = (const float*)d_in[1];
    float* out = (float*)d_out;

    cudaFuncSetAttribute(ncc_main_kernel,
                         cudaFuncAttributeMaxDynamicSharedMemorySize, SMEM_BYTES);
    dim3 grid(GX, GY, NB);
    ncc_main_kernel<<<grid, TPB, SMEM_BYTES>>>(I, J, out);
}